// round 6
// baseline (speedup 1.0000x reference)
#include <cuda_runtime.h>
#include <cstdint>

// B=16, N=3136 (56x56), C=384, NH=12, hd=32, WS=7, nW=1024, S=49.
#define M_TOK   50176
#define C_DIM   384
#define QKV_DIM 1152
#define K_DIM   384

// Scratch (device globals: allocation-free)
static __device__ float g_x  [(size_t)M_TOK * C_DIM];
static __device__ float g_qkv[(size_t)M_TOK * QKV_DIM];
static __device__ float g_att[(size_t)M_TOK * C_DIM];
static __device__ float g_wqkv[QKV_DIM * C_DIM];
static __device__ float g_wproj[C_DIM * C_DIM];

__device__ __forceinline__ float tf32r(float x) {
    uint32_t u;
    asm("cvt.rna.tf32.f32 %0, %1;" : "=r"(u) : "f"(x));
    return __uint_as_float(u);
}

__device__ __forceinline__ void mma_tf32(float c[4],
                                         uint32_t a0, uint32_t a1, uint32_t a2, uint32_t a3,
                                         uint32_t b0, uint32_t b1) {
    asm volatile(
        "mma.sync.aligned.m16n8k8.row.col.f32.tf32.tf32.f32 "
        "{%0,%1,%2,%3}, {%4,%5,%6,%7}, {%8,%9}, {%0,%1,%2,%3};\n"
        : "+f"(c[0]), "+f"(c[1]), "+f"(c[2]), "+f"(c[3])
        : "r"(a0), "r"(a1), "r"(a2), "r"(a3), "r"(b0), "r"(b1));
}

__device__ __forceinline__ void cp16(uint32_t smem_addr, const float* gptr) {
    asm volatile("cp.async.cg.shared.global [%0], [%1], 16;\n"
                 :: "r"(smem_addr), "l"(gptr));
}

// ---------------------------------------------------------------------------
// Prepass: elementwise tf32 rounding (float4 streaming)
// ---------------------------------------------------------------------------
__global__ void cvt_kernel(const float* __restrict__ src, float* __restrict__ dst, int n4)
{
    int i = blockIdx.x * blockDim.x + threadIdx.x;
    if (i < n4) {
        float4 v = reinterpret_cast<const float4*>(src)[i];
        v.x = tf32r(v.x); v.y = tf32r(v.y); v.z = tf32r(v.z); v.w = tf32r(v.w);
        reinterpret_cast<float4*>(dst)[i] = v;
    }
}

// ---------------------------------------------------------------------------
// GEMM:  C[m,n] = sum_k A[m,k]*B[n,k] (+bias[n]).  A,B pre-rounded to tf32.
// BM=128, BN=128, BK=32, 3-stage cp.async pipeline, XOR-swizzled smem
// (128B rows, no padding -> 32KB/stage, 96KB total -> 2 CTAs/SM).
// 8 warps: 4 along M (32 rows) x 2 along N (64 cols); warp = 2x8 m16n8k8.
// ---------------------------------------------------------------------------
#define GSTAGES    3
#define STAGE_F    (256 * 32)          // floats per stage: A 128x32 + B 128x32
#define SMEM_BYTES (GSTAGES * STAGE_F * 4)   // 98304

// swizzled float index for logical (row, col) in a 128x32 tile
__device__ __forceinline__ int swidx(int r, int col) {
    return r * 32 + ((((col >> 2) ^ (r & 7)) << 2) | (col & 3));
}

template<bool HAS_BIAS>
__global__ __launch_bounds__(256, 2) void gemm_tn_kernel(
    const float* __restrict__ A, const float* __restrict__ B,
    const float* __restrict__ bias, float* __restrict__ Cout, int N)
{
    extern __shared__ float smem[];

    const int tid  = threadIdx.x;
    const int lane = tid & 31;
    const int warp = tid >> 5;
    const int wm   = warp & 3;          // 0..3 along M
    const int wn   = warp >> 2;         // 0..1 along N
    const int g    = lane >> 2;
    const int t4   = lane & 3;

    const long bm = (long)blockIdx.y * 128;
    const long bn = (long)blockIdx.x * 128;

    const int lrow = tid >> 1;          // 0..127
    const int lcp  = (tid & 1) * 4;     // first 16B-chunk index (0 or 4)

    float acc[2][8][4];
    #pragma unroll
    for (int i = 0; i < 2; i++)
        #pragma unroll
        for (int j = 0; j < 8; j++)
            #pragma unroll
            for (int k = 0; k < 4; k++) acc[i][j][k] = 0.f;

    const float* gA = A + (bm + lrow) * (long)K_DIM;
    const float* gB = B + (bn + lrow) * (long)K_DIM;
    const uint32_t rowoff = lrow * 128;          // byte offset of row
    const int      rxor   = lrow & 7;

    auto issue = [&](int stg, int kb) {
        uint32_t dA = (uint32_t)__cvta_generic_to_shared(smem + stg * STAGE_F);
        uint32_t dB = dA + 128 * 32 * 4;
        #pragma unroll
        for (int c = 0; c < 4; c++) {
            uint32_t off = rowoff + (((lcp + c) ^ rxor) << 4);
            cp16(dA + off, gA + kb + (lcp + c) * 4);
            cp16(dB + off, gB + kb + (lcp + c) * 4);
        }
        asm volatile("cp.async.commit_group;\n");
    };

    issue(0, 0);
    issue(1, 32);

    for (int k = 0; k < 12; k++) {
        if (k < 10) asm volatile("cp.async.wait_group 1;\n");
        else        asm volatile("cp.async.wait_group 0;\n");
        __syncthreads();

        if (k + 2 < 12) issue((k + 2) % 3, (k + 2) * 32);

        const float* cA = smem + (k % 3) * STAGE_F;
        const float* cB = cA + 128 * 32;

        #pragma unroll
        for (int kk = 0; kk < 32; kk += 8) {
            uint32_t a[2][4];
            #pragma unroll
            for (int mt = 0; mt < 2; mt++) {
                int m = wm * 32 + mt * 16;
                a[mt][0] = __float_as_uint(cA[swidx(m + g,     kk + t4    )]);
                a[mt][1] = __float_as_uint(cA[swidx(m + g + 8, kk + t4    )]);
                a[mt][2] = __float_as_uint(cA[swidx(m + g,     kk + t4 + 4)]);
                a[mt][3] = __float_as_uint(cA[swidx(m + g + 8, kk + t4 + 4)]);
            }
            uint32_t bf[8][2];
            #pragma unroll
            for (int nt = 0; nt < 8; nt++) {
                int n = wn * 64 + nt * 8;
                bf[nt][0] = __float_as_uint(cB[swidx(n + g, kk + t4    )]);
                bf[nt][1] = __float_as_uint(cB[swidx(n + g, kk + t4 + 4)]);
            }
            #pragma unroll
            for (int mt = 0; mt < 2; mt++)
                #pragma unroll
                for (int nt = 0; nt < 8; nt++)
                    mma_tf32(acc[mt][nt], a[mt][0], a[mt][1], a[mt][2], a[mt][3],
                             bf[nt][0], bf[nt][1]);
        }
        __syncthreads();
    }

    #pragma unroll
    for (int mt = 0; mt < 2; mt++) {
        #pragma unroll
        for (int nt = 0; nt < 8; nt++) {
            long row = bm + wm * 32 + mt * 16 + g;
            long col = bn + wn * 64 + nt * 8 + 2 * t4;
            float b0 = 0.f, b1 = 0.f;
            if (HAS_BIAS) { b0 = bias[col]; b1 = bias[col + 1]; }
            *reinterpret_cast<float2*>(Cout + row * (long)N + col) =
                make_float2(acc[mt][nt][0] + b0, acc[mt][nt][1] + b1);
            *reinterpret_cast<float2*>(Cout + (row + 8) * (long)N + col) =
                make_float2(acc[mt][nt][2] + b0, acc[mt][nt][3] + b1);
        }
    }
}

// ---------------------------------------------------------------------------
// Windowed attention (unchanged): one CTA per (head, window). S=49 pad 64.
// ---------------------------------------------------------------------------
__global__ __launch_bounds__(256) void attn_kernel()
{
    __shared__ float qs[64][36];
    __shared__ float ks[64][36];
    __shared__ float vT[32][68];
    __shared__ float ps[64][68];

    const int tid  = threadIdx.x;
    const int lane = tid & 31;
    const int warp = tid >> 5;
    const int g    = lane >> 2;
    const int t4   = lane & 3;

    const int h = blockIdx.x;
    const int w = blockIdx.y;
    const int b   = w >> 6;
    const int whh = (w >> 3) & 7;
    const int ww  = w & 7;
    const int tbase = b * 3136 + whh * 392 + ww * 7;
    const float scale = 0.17677669529663687f;   // 1/sqrt(32)

    for (int i = tid; i < 32 * 16; i += 256) {
        int d = i >> 4, c = 49 + (i & 15);
        vT[d][c] = 0.f;
    }

    for (int idx = tid; idx < 392; idx += 256) {
        int s = idx >> 3, dd = (idx & 7) << 2;
        int tok = tbase + (s / 7) * 56 + (s % 7);
        const float* p = g_qkv + (long)tok * QKV_DIM + h * 32 + dd;
        float4 q4 = *reinterpret_cast<const float4*>(p);
        float4 k4 = *reinterpret_cast<const float4*>(p + 384);
        float4 v4 = *reinterpret_cast<const float4*>(p + 768);
        qs[s][dd    ] = tf32r(q4.x * scale);
        qs[s][dd + 1] = tf32r(q4.y * scale);
        qs[s][dd + 2] = tf32r(q4.z * scale);
        qs[s][dd + 3] = tf32r(q4.w * scale);
        ks[s][dd    ] = tf32r(k4.x);
        ks[s][dd + 1] = tf32r(k4.y);
        ks[s][dd + 2] = tf32r(k4.z);
        ks[s][dd + 3] = tf32r(k4.w);
        vT[dd    ][s] = tf32r(v4.x);
        vT[dd + 1][s] = tf32r(v4.y);
        vT[dd + 2][s] = tf32r(v4.z);
        vT[dd + 3][s] = tf32r(v4.w);
    }
    __syncthreads();

    {
        float acc[4][4];
        #pragma unroll
        for (int j = 0; j < 4; j++)
            #pragma unroll
            for (int k = 0; k < 4; k++) acc[j][k] = 0.f;

        const int m = (warp & 3) * 16;
        #pragma unroll
        for (int kk = 0; kk < 32; kk += 8) {
            uint32_t a0 = __float_as_uint(qs[m + g    ][kk + t4    ]);
            uint32_t a1 = __float_as_uint(qs[m + g + 8][kk + t4    ]);
            uint32_t a2 = __float_as_uint(qs[m + g    ][kk + t4 + 4]);
            uint32_t a3 = __float_as_uint(qs[m + g + 8][kk + t4 + 4]);
            #pragma unroll
            for (int nt = 0; nt < 4; nt++) {
                int n = (warp >> 2) * 32 + nt * 8;
                uint32_t b0 = __float_as_uint(ks[n + g][kk + t4    ]);
                uint32_t b1 = __float_as_uint(ks[n + g][kk + t4 + 4]);
                mma_tf32(acc[nt], a0, a1, a2, a3, b0, b1);
            }
        }
        #pragma unroll
        for (int nt = 0; nt < 4; nt++) {
            int row = (warp & 3) * 16 + g;
            int col = (warp >> 2) * 32 + nt * 8 + 2 * t4;
            *reinterpret_cast<float2*>(&ps[row][col])     = make_float2(acc[nt][0], acc[nt][1]);
            *reinterpret_cast<float2*>(&ps[row + 8][col]) = make_float2(acc[nt][2], acc[nt][3]);
        }
    }
    __syncthreads();

    for (int r = warp; r < 49; r += 8) {
        float s0 = ps[r][lane];
        float s1 = ps[r][lane + 32];
        bool  v1 = (lane + 32) < 49;
        float mx = fmaxf(s0, v1 ? s1 : -1e30f);
        #pragma unroll
        for (int o = 16; o; o >>= 1) mx = fmaxf(mx, __shfl_xor_sync(0xffffffffu, mx, o));
        float e0 = __expf(s0 - mx);
        float e1 = v1 ? __expf(s1 - mx) : 0.f;
        float sm = e0 + e1;
        #pragma unroll
        for (int o = 16; o; o >>= 1) sm += __shfl_xor_sync(0xffffffffu, sm, o);
        float inv = 1.f / sm;
        ps[r][lane]      = tf32r(e0 * inv);
        ps[r][lane + 32] = tf32r(e1 * inv);
    }
    __syncthreads();

    {
        float acc[2][4];
        #pragma unroll
        for (int j = 0; j < 2; j++)
            #pragma unroll
            for (int k = 0; k < 4; k++) acc[j][k] = 0.f;

        const int m = (warp & 3) * 16;
        #pragma unroll
        for (int kk = 0; kk < 64; kk += 8) {
            uint32_t a0 = __float_as_uint(ps[m + g    ][kk + t4    ]);
            uint32_t a1 = __float_as_uint(ps[m + g + 8][kk + t4    ]);
            uint32_t a2 = __float_as_uint(ps[m + g    ][kk + t4 + 4]);
            uint32_t a3 = __float_as_uint(ps[m + g + 8][kk + t4 + 4]);
            #pragma unroll
            for (int j = 0; j < 2; j++) {
                int n = (warp >> 2) * 16 + j * 8;
                uint32_t b0 = __float_as_uint(vT[n + g][kk + t4    ]);
                uint32_t b1 = __float_as_uint(vT[n + g][kk + t4 + 4]);
                mma_tf32(acc[j], a0, a1, a2, a3, b0, b1);
            }
        }
        #pragma unroll
        for (int j = 0; j < 2; j++) {
            int col = (warp >> 2) * 16 + j * 8 + 2 * t4;
            #pragma unroll
            for (int i = 0; i < 2; i++) {
                int r = m + g + i * 8;
                if (r < 49) {
                    int tok = tbase + (r / 7) * 56 + (r % 7);
                    *reinterpret_cast<float2*>(g_att + (long)tok * C_DIM + h * 32 + col) =
                        make_float2(tf32r(acc[j][0 + 2 * i]), tf32r(acc[j][1 + 2 * i]));
                }
            }
        }
    }
}

// ---------------------------------------------------------------------------
extern "C" void kernel_launch(void* const* d_in, const int* in_sizes, int n_in,
                              void* d_out, int out_size)
{
    const float* x      = (const float*)d_in[0];
    const float* w_qkv  = (const float*)d_in[1];
    const float* w_proj = (const float*)d_in[2];
    const float* b_proj = (const float*)d_in[3];
    float* out = (float*)d_out;

    float *xp, *qkvp, *attp, *wqkvp, *wprojp;
    cudaGetSymbolAddress((void**)&xp,     g_x);
    cudaGetSymbolAddress((void**)&qkvp,   g_qkv);
    cudaGetSymbolAddress((void**)&attp,   g_att);
    cudaGetSymbolAddress((void**)&wqkvp,  g_wqkv);
    cudaGetSymbolAddress((void**)&wprojp, g_wproj);

    cudaFuncSetAttribute(gemm_tn_kernel<false>,
                         cudaFuncAttributeMaxDynamicSharedMemorySize, SMEM_BYTES);
    cudaFuncSetAttribute(gemm_tn_kernel<true>,
                         cudaFuncAttributeMaxDynamicSharedMemorySize, SMEM_BYTES);

    // 0) tf32-rounding prepass
    cvt_kernel<<<(M_TOK * C_DIM / 4) / 256, 256>>>(x, xp, M_TOK * C_DIM / 4);
    cvt_kernel<<<(QKV_DIM * C_DIM / 4 + 255) / 256, 256>>>(w_qkv, wqkvp, QKV_DIM * C_DIM / 4);
    cvt_kernel<<<(C_DIM * C_DIM / 4 + 255) / 256, 256>>>(w_proj, wprojp, C_DIM * C_DIM / 4);

    // 1) QKV projection: [50176 x 384] @ [384 x 1152]
    gemm_tn_kernel<false><<<dim3(QKV_DIM / 128, M_TOK / 128), 256, SMEM_BYTES>>>(
        xp, wqkvp, nullptr, qkvp, QKV_DIM);

    // 2) Windowed attention
    attn_kernel<<<dim3(12, 1024), 256>>>();

    // 3) Output projection + bias: [50176 x 384] @ [384 x 384]
    gemm_tn_kernel<true><<<dim3(C_DIM / 128, M_TOK / 128), 256, SMEM_BYTES>>>(
        attp, wprojp, b_proj, out, C_DIM);
}

// round 7
// speedup vs baseline: 1.6139x; 1.6139x over previous
#include <cuda_runtime.h>
#include <cstdint>

// B=16, N=3136 (56x56), C=384, NH=12, hd=32, WS=7, nW=1024, S=49.
#define M_TOK   50176
#define C_DIM   384
#define QKV_DIM 1152
#define K_DIM   384

// Scratch (device globals: allocation-free)
static __device__ float g_x  [(size_t)M_TOK * C_DIM];
static __device__ float g_qkv[(size_t)M_TOK * QKV_DIM];
static __device__ float g_att[(size_t)M_TOK * C_DIM];
static __device__ float g_wqkv[QKV_DIM * C_DIM];
static __device__ float g_wproj[C_DIM * C_DIM];

__device__ __forceinline__ float tf32r(float x) {
    uint32_t u;
    asm("cvt.rna.tf32.f32 %0, %1;" : "=r"(u) : "f"(x));
    return __uint_as_float(u);
}

__device__ __forceinline__ void mma_tf32(float c[4],
                                         uint32_t a0, uint32_t a1, uint32_t a2, uint32_t a3,
                                         uint32_t b0, uint32_t b1) {
    asm volatile(
        "mma.sync.aligned.m16n8k8.row.col.f32.tf32.tf32.f32 "
        "{%0,%1,%2,%3}, {%4,%5,%6,%7}, {%8,%9}, {%0,%1,%2,%3};\n"
        : "+f"(c[0]), "+f"(c[1]), "+f"(c[2]), "+f"(c[3])
        : "r"(a0), "r"(a1), "r"(a2), "r"(a3), "r"(b0), "r"(b1));
}

__device__ __forceinline__ void ldm_x4(uint32_t& d0, uint32_t& d1, uint32_t& d2, uint32_t& d3,
                                       uint32_t addr) {
    asm volatile("ldmatrix.sync.aligned.m8n8.x4.shared.b16 {%0,%1,%2,%3}, [%4];"
                 : "=r"(d0), "=r"(d1), "=r"(d2), "=r"(d3) : "r"(addr));
}

__device__ __forceinline__ void cp16(uint32_t smem_addr, const float* gptr) {
    asm volatile("cp.async.cg.shared.global [%0], [%1], 16;\n"
                 :: "r"(smem_addr), "l"(gptr));
}

// ---------------------------------------------------------------------------
// Prepass: elementwise tf32 rounding (float4 streaming)
// ---------------------------------------------------------------------------
__global__ void cvt_kernel(const float* __restrict__ src, float* __restrict__ dst, int n4)
{
    int i = blockIdx.x * blockDim.x + threadIdx.x;
    if (i < n4) {
        float4 v = reinterpret_cast<const float4*>(src)[i];
        v.x = tf32r(v.x); v.y = tf32r(v.y); v.z = tf32r(v.z); v.w = tf32r(v.w);
        reinterpret_cast<float4*>(dst)[i] = v;
    }
}

// ---------------------------------------------------------------------------
// GEMM:  C[m,n] = sum_k A[m,k]*B[n,k] (+bias[n]).  A,B pre-rounded to tf32.
// BM=128, BN=128, BK=32, 3-stage cp.async pipeline, stride-36 padded smem
// (144B rows: affine LDS offsets + conflict-free ldmatrix phases).
// 8 warps: 4 along M x 2 along N; warp = 2x8 m16n8k8 tiles.
// Fragments loaded via ldmatrix.x4 (6 per K-step instead of 24 LDS).
// ---------------------------------------------------------------------------
#define STAGE_F (128 * 36 * 2)                 // floats per stage (A + B tile)
#define SMEM_BYTES (3 * STAGE_F * 4)           // 110592 -> 2 CTAs/SM

template<bool HAS_BIAS>
__global__ __launch_bounds__(256, 2) void gemm_tn_kernel(
    const float* __restrict__ A, const float* __restrict__ B,
    const float* __restrict__ bias, float* __restrict__ Cout, int N)
{
    extern __shared__ float smem[];

    const int tid  = threadIdx.x;
    const int lane = tid & 31;
    const int warp = tid >> 5;
    const int wm   = warp & 3;          // 0..3 along M
    const int wn   = warp >> 2;         // 0..1 along N
    const int g    = lane >> 2;
    const int t4   = lane & 3;

    const long bm = (long)blockIdx.y * 128;
    const long bn = (long)blockIdx.x * 128;

    const int lr = tid >> 3;            // 0..31
    const int lc = (tid & 7) << 2;      // 0,4,..,28

    float acc[2][8][4];
    #pragma unroll
    for (int i = 0; i < 2; i++)
        #pragma unroll
        for (int j = 0; j < 8; j++)
            #pragma unroll
            for (int k = 0; k < 4; k++) acc[i][j][k] = 0.f;

    const float* gA = A + (bm + lr) * (long)K_DIM + lc;
    const float* gB = B + (bn + lr) * (long)K_DIM + lc;

    auto issue = [&](int stg, int kb) {
        float* dA = smem + stg * STAGE_F;
        float* dB = dA + 128 * 36;
        #pragma unroll
        for (int i = 0; i < 4; i++)
            cp16((uint32_t)__cvta_generic_to_shared(dA + (lr + i * 32) * 36 + lc),
                 gA + (long)i * 32 * K_DIM + kb);
        #pragma unroll
        for (int i = 0; i < 4; i++)
            cp16((uint32_t)__cvta_generic_to_shared(dB + (lr + i * 32) * 36 + lc),
                 gB + (long)i * 32 * K_DIM + kb);
        asm volatile("cp.async.commit_group;\n");
    };

    // per-lane ldmatrix base offsets (bytes within a stage's A / B tile)
    // lane -> matrix index mi (0..3) and row-in-matrix ri (0..7)
    const int mi = lane >> 3, ri = lane & 7;
    // A, tile mt: matrices = (rows m+{0,8}+ri) x (col quads kk/4 + {0,1})
    //   mi=0:(+0,+0) mi=1:(+8,+0) mi=2:(+0,+16B) mi=3:(+8,+16B)
    const uint32_t aOff = ((wm * 32 + ((mi & 1) << 3) + ri) * 36 + ((mi >> 1) << 2)) * 4;
    // B, pair p: mi=0:(+0,+0) mi=1:(+0,+16B) mi=2:(+8,+0) mi=3:(+8,+16B)
    uint32_t bOff[4];
    #pragma unroll
    for (int p = 0; p < 4; p++)
        bOff[p] = ((wn * 64 + p * 16 + ((mi >> 1) << 3) + ri) * 36 + ((mi & 1) << 2)) * 4;

    const uint32_t sbase = (uint32_t)__cvta_generic_to_shared(smem);

    issue(0, 0);
    issue(1, 32);

    for (int k = 0; k < 12; k++) {
        if (k < 10) asm volatile("cp.async.wait_group 1;\n");
        else        asm volatile("cp.async.wait_group 0;\n");
        __syncthreads();

        if (k + 2 < 12) issue((k + 2) % 3, (k + 2) * 32);

        const uint32_t stA = sbase + (k % 3) * (STAGE_F * 4);
        const uint32_t stB = stA + 128 * 36 * 4;

        #pragma unroll
        for (int kk = 0; kk < 32; kk += 8) {
            uint32_t a[2][4];
            #pragma unroll
            for (int mt = 0; mt < 2; mt++)
                ldm_x4(a[mt][0], a[mt][1], a[mt][2], a[mt][3],
                       stA + aOff + mt * (16 * 144) + kk * 4);

            uint32_t bf[8][2];
            #pragma unroll
            for (int p = 0; p < 4; p++) {
                uint32_t d0, d1, d2, d3;
                ldm_x4(d0, d1, d2, d3, stB + bOff[p] + kk * 4);
                bf[2 * p    ][0] = d0; bf[2 * p    ][1] = d1;
                bf[2 * p + 1][0] = d2; bf[2 * p + 1][1] = d3;
            }

            #pragma unroll
            for (int mt = 0; mt < 2; mt++)
                #pragma unroll
                for (int nt = 0; nt < 8; nt++)
                    mma_tf32(acc[mt][nt], a[mt][0], a[mt][1], a[mt][2], a[mt][3],
                             bf[nt][0], bf[nt][1]);
        }
        __syncthreads();
    }

    #pragma unroll
    for (int mt = 0; mt < 2; mt++) {
        #pragma unroll
        for (int nt = 0; nt < 8; nt++) {
            long row = bm + wm * 32 + mt * 16 + g;
            long col = bn + wn * 64 + nt * 8 + 2 * t4;
            float b0 = 0.f, b1 = 0.f;
            if (HAS_BIAS) { b0 = bias[col]; b1 = bias[col + 1]; }
            *reinterpret_cast<float2*>(Cout + row * (long)N + col) =
                make_float2(acc[mt][nt][0] + b0, acc[mt][nt][1] + b1);
            *reinterpret_cast<float2*>(Cout + (row + 8) * (long)N + col) =
                make_float2(acc[mt][nt][2] + b0, acc[mt][nt][3] + b1);
        }
    }
}

// ---------------------------------------------------------------------------
// Windowed attention (unchanged): one CTA per (head, window). S=49 pad 64.
// ---------------------------------------------------------------------------
__global__ __launch_bounds__(256) void attn_kernel()
{
    __shared__ float qs[64][36];
    __shared__ float ks[64][36];
    __shared__ float vT[32][68];
    __shared__ float ps[64][68];

    const int tid  = threadIdx.x;
    const int lane = tid & 31;
    const int warp = tid >> 5;
    const int g    = lane >> 2;
    const int t4   = lane & 3;

    const int h = blockIdx.x;
    const int w = blockIdx.y;
    const int b   = w >> 6;
    const int whh = (w >> 3) & 7;
    const int ww  = w & 7;
    const int tbase = b * 3136 + whh * 392 + ww * 7;
    const float scale = 0.17677669529663687f;   // 1/sqrt(32)

    for (int i = tid; i < 32 * 16; i += 256) {
        int d = i >> 4, c = 49 + (i & 15);
        vT[d][c] = 0.f;
    }

    for (int idx = tid; idx < 392; idx += 256) {
        int s = idx >> 3, dd = (idx & 7) << 2;
        int tok = tbase + (s / 7) * 56 + (s % 7);
        const float* p = g_qkv + (long)tok * QKV_DIM + h * 32 + dd;
        float4 q4 = *reinterpret_cast<const float4*>(p);
        float4 k4 = *reinterpret_cast<const float4*>(p + 384);
        float4 v4 = *reinterpret_cast<const float4*>(p + 768);
        qs[s][dd    ] = tf32r(q4.x * scale);
        qs[s][dd + 1] = tf32r(q4.y * scale);
        qs[s][dd + 2] = tf32r(q4.z * scale);
        qs[s][dd + 3] = tf32r(q4.w * scale);
        ks[s][dd    ] = tf32r(k4.x);
        ks[s][dd + 1] = tf32r(k4.y);
        ks[s][dd + 2] = tf32r(k4.z);
        ks[s][dd + 3] = tf32r(k4.w);
        vT[dd    ][s] = tf32r(v4.x);
        vT[dd + 1][s] = tf32r(v4.y);
        vT[dd + 2][s] = tf32r(v4.z);
        vT[dd + 3][s] = tf32r(v4.w);
    }
    __syncthreads();

    {
        float acc[4][4];
        #pragma unroll
        for (int j = 0; j < 4; j++)
            #pragma unroll
            for (int k = 0; k < 4; k++) acc[j][k] = 0.f;

        const int m = (warp & 3) * 16;
        #pragma unroll
        for (int kk = 0; kk < 32; kk += 8) {
            uint32_t a0 = __float_as_uint(qs[m + g    ][kk + t4    ]);
            uint32_t a1 = __float_as_uint(qs[m + g + 8][kk + t4    ]);
            uint32_t a2 = __float_as_uint(qs[m + g    ][kk + t4 + 4]);
            uint32_t a3 = __float_as_uint(qs[m + g + 8][kk + t4 + 4]);
            #pragma unroll
            for (int nt = 0; nt < 4; nt++) {
                int n = (warp >> 2) * 32 + nt * 8;
                uint32_t b0 = __float_as_uint(ks[n + g][kk + t4    ]);
                uint32_t b1 = __float_as_uint(ks[n + g][kk + t4 + 4]);
                mma_tf32(acc[nt], a0, a1, a2, a3, b0, b1);
            }
        }
        #pragma unroll
        for (int nt = 0; nt < 4; nt++) {
            int row = (warp & 3) * 16 + g;
            int col = (warp >> 2) * 32 + nt * 8 + 2 * t4;
            *reinterpret_cast<float2*>(&ps[row][col])     = make_float2(acc[nt][0], acc[nt][1]);
            *reinterpret_cast<float2*>(&ps[row + 8][col]) = make_float2(acc[nt][2], acc[nt][3]);
        }
    }
    __syncthreads();

    for (int r = warp; r < 49; r += 8) {
        float s0 = ps[r][lane];
        float s1 = ps[r][lane + 32];
        bool  v1 = (lane + 32) < 49;
        float mx = fmaxf(s0, v1 ? s1 : -1e30f);
        #pragma unroll
        for (int o = 16; o; o >>= 1) mx = fmaxf(mx, __shfl_xor_sync(0xffffffffu, mx, o));
        float e0 = __expf(s0 - mx);
        float e1 = v1 ? __expf(s1 - mx) : 0.f;
        float sm = e0 + e1;
        #pragma unroll
        for (int o = 16; o; o >>= 1) sm += __shfl_xor_sync(0xffffffffu, sm, o);
        float inv = 1.f / sm;
        ps[r][lane]      = tf32r(e0 * inv);
        ps[r][lane + 32] = tf32r(e1 * inv);
    }
    __syncthreads();

    {
        float acc[2][4];
        #pragma unroll
        for (int j = 0; j < 2; j++)
            #pragma unroll
            for (int k = 0; k < 4; k++) acc[j][k] = 0.f;

        const int m = (warp & 3) * 16;
        #pragma unroll
        for (int kk = 0; kk < 64; kk += 8) {
            uint32_t a0 = __float_as_uint(ps[m + g    ][kk + t4    ]);
            uint32_t a1 = __float_as_uint(ps[m + g + 8][kk + t4    ]);
            uint32_t a2 = __float_as_uint(ps[m + g    ][kk + t4 + 4]);
            uint32_t a3 = __float_as_uint(ps[m + g + 8][kk + t4 + 4]);
            #pragma unroll
            for (int j = 0; j < 2; j++) {
                int n = (warp >> 2) * 16 + j * 8;
                uint32_t b0 = __float_as_uint(vT[n + g][kk + t4    ]);
                uint32_t b1 = __float_as_uint(vT[n + g][kk + t4 + 4]);
                mma_tf32(acc[j], a0, a1, a2, a3, b0, b1);
            }
        }
        #pragma unroll
        for (int j = 0; j < 2; j++) {
            int col = (warp >> 2) * 16 + j * 8 + 2 * t4;
            #pragma unroll
            for (int i = 0; i < 2; i++) {
                int r = m + g + i * 8;
                if (r < 49) {
                    int tok = tbase + (r / 7) * 56 + (r % 7);
                    *reinterpret_cast<float2*>(g_att + (long)tok * C_DIM + h * 32 + col) =
                        make_float2(tf32r(acc[j][0 + 2 * i]), tf32r(acc[j][1 + 2 * i]));
                }
            }
        }
    }
}

// ---------------------------------------------------------------------------
extern "C" void kernel_launch(void* const* d_in, const int* in_sizes, int n_in,
                              void* d_out, int out_size)
{
    const float* x      = (const float*)d_in[0];
    const float* w_qkv  = (const float*)d_in[1];
    const float* w_proj = (const float*)d_in[2];
    const float* b_proj = (const float*)d_in[3];
    float* out = (float*)d_out;

    float *xp, *qkvp, *attp, *wqkvp, *wprojp;
    cudaGetSymbolAddress((void**)&xp,     g_x);
    cudaGetSymbolAddress((void**)&qkvp,   g_qkv);
    cudaGetSymbolAddress((void**)&attp,   g_att);
    cudaGetSymbolAddress((void**)&wqkvp,  g_wqkv);
    cudaGetSymbolAddress((void**)&wprojp, g_wproj);

    cudaFuncSetAttribute(gemm_tn_kernel<false>,
                         cudaFuncAttributeMaxDynamicSharedMemorySize, SMEM_BYTES);
    cudaFuncSetAttribute(gemm_tn_kernel<true>,
                         cudaFuncAttributeMaxDynamicSharedMemorySize, SMEM_BYTES);

    // 0) tf32-rounding prepass
    cvt_kernel<<<(M_TOK * C_DIM / 4) / 256, 256>>>(x, xp, M_TOK * C_DIM / 4);
    cvt_kernel<<<(QKV_DIM * C_DIM / 4 + 255) / 256, 256>>>(w_qkv, wqkvp, QKV_DIM * C_DIM / 4);
    cvt_kernel<<<(C_DIM * C_DIM / 4 + 255) / 256, 256>>>(w_proj, wprojp, C_DIM * C_DIM / 4);

    // 1) QKV projection: [50176 x 384] @ [384 x 1152]
    gemm_tn_kernel<false><<<dim3(QKV_DIM / 128, M_TOK / 128), 256, SMEM_BYTES>>>(
        xp, wqkvp, nullptr, qkvp, QKV_DIM);

    // 2) Windowed attention
    attn_kernel<<<dim3(12, 1024), 256>>>();

    // 3) Output projection + bias: [50176 x 384] @ [384 x 384]
    gemm_tn_kernel<true><<<dim3(C_DIM / 128, M_TOK / 128), 256, SMEM_BYTES>>>(
        attp, wprojp, b_proj, out, C_DIM);
}